// round 1
// baseline (speedup 1.0000x reference)
#include <cuda_runtime.h>

// ---------------------------------------------------------------------------
// GPT block: x:[4,2048,1024]
//   h = LN1(x); qkv = h@w_attn + b_attn
//   att = softmax(causal(q@k^T * 1/8)); y = att@v
//   x1 = x + y@w_proj + b_proj
//   h2 = LN2(x1); m = gelu(h2@w_fc + b_fc)
//   out = x1 + m@w_fc2 + b_fc2
// All GEMMs in TF32 mma.sync (fp32 accum). Scratch in __device__ globals.
// ---------------------------------------------------------------------------

#define D_MODEL 1024
#define T_SEQ   2048
#define N_BATCH 4
#define ROWS    (N_BATCH * T_SEQ)   // 8192

__device__ float g_h[ROWS * D_MODEL];
__device__ float g_qkv[ROWS * 3 * D_MODEL];
__device__ float g_scores[(size_t)N_BATCH * T_SEQ * T_SEQ];
__device__ float g_y[ROWS * D_MODEL];
__device__ float g_mlp[(size_t)ROWS * 4 * D_MODEL];

#define BM 128
#define BN 128
#define BK 16

__device__ __forceinline__ unsigned tf32bits(float x) {
    unsigned u;
    asm("cvt.rna.tf32.f32 %0, %1;" : "=r"(u) : "f"(x));
    return u;
}

__device__ __forceinline__ void mma_m16n8k8(float* c, const unsigned* a, const unsigned* b) {
    asm volatile(
        "mma.sync.aligned.m16n8k8.row.col.f32.tf32.tf32.f32 "
        "{%0,%1,%2,%3}, {%4,%5,%6,%7}, {%8,%9}, {%0,%1,%2,%3};\n"
        : "+f"(c[0]), "+f"(c[1]), "+f"(c[2]), "+f"(c[3])
        : "r"(a[0]), "r"(a[1]), "r"(a[2]), "r"(a[3]),
          "r"(b[0]), "r"(b[1]));
}

__device__ __forceinline__ float gelu_tanh(float x) {
    float x3 = x * x * x;
    return 0.5f * x * (1.0f + tanhf(0.7978845608028654f * (x + 0.044715f * x3)));
}

// C[M,N] = A[M,K] @ (TRANS_B ? B[N,K]^T : B[K,N]) (+ bias) (+ gelu) (+ Res)
// grid = (N/BN, M/BM, batch); 256 threads.
template<bool TRANS_B, int EPI>
__global__ __launch_bounds__(256)
void gemm_kernel(const float* __restrict__ A, const float* __restrict__ B,
                 const float* __restrict__ bias, const float* __restrict__ Res,
                 float* __restrict__ C,
                 int K, int lda, int ldb, int ldc,
                 long long sA, long long sB, long long sC)
{
    A += (long long)blockIdx.z * sA;
    B += (long long)blockIdx.z * sB;
    C += (long long)blockIdx.z * sC;

    __shared__ __align__(16) unsigned As[2][BK][BM + 4];
    __shared__ __align__(16) unsigned Bs[2][BK][BN + 4];

    const int tid  = threadIdx.x;
    const int lane = tid & 31;
    const int wid  = tid >> 5;
    const int wm   = (wid >> 2) * 64;   // 2 warps along M
    const int wn   = (wid & 3) * 32;    // 4 warps along N
    const int bm0  = blockIdx.y * BM;
    const int bn0  = blockIdx.x * BN;

    float acc[4][4][4];
    #pragma unroll
    for (int i = 0; i < 4; i++)
        #pragma unroll
        for (int j = 0; j < 4; j++)
            #pragma unroll
            for (int k = 0; k < 4; k++) acc[i][j][k] = 0.0f;

    const int arow0 = tid >> 2;   // 0..63
    const int acol4 = tid & 3;    // 0..3 (float4 index within 16-wide k tile)

    float4 ra[2], rb[2];

    auto loadG = [&](int kt) {
        const int k0 = kt * BK;
        #pragma unroll
        for (int j = 0; j < 2; j++) {
            int row = arow0 + j * 64;
            ra[j] = *reinterpret_cast<const float4*>(
                A + (long long)(bm0 + row) * lda + k0 + acol4 * 4);
        }
        if (TRANS_B) {
            #pragma unroll
            for (int j = 0; j < 2; j++) {
                int row = arow0 + j * 64;
                rb[j] = *reinterpret_cast<const float4*>(
                    B + (long long)(bn0 + row) * ldb + k0 + acol4 * 4);
            }
        } else {
            const int brow = tid >> 5;      // 0..7
            const int bc4  = tid & 31;      // 0..31
            #pragma unroll
            for (int j = 0; j < 2; j++) {
                rb[j] = *reinterpret_cast<const float4*>(
                    B + (long long)(k0 + brow + j * 8) * ldb + bn0 + bc4 * 4);
            }
        }
    };

    auto storeS = [&](int buf) {
        #pragma unroll
        for (int j = 0; j < 2; j++) {
            int row = arow0 + j * 64;
            As[buf][acol4 * 4 + 0][row] = tf32bits(ra[j].x);
            As[buf][acol4 * 4 + 1][row] = tf32bits(ra[j].y);
            As[buf][acol4 * 4 + 2][row] = tf32bits(ra[j].z);
            As[buf][acol4 * 4 + 3][row] = tf32bits(ra[j].w);
        }
        if (TRANS_B) {
            #pragma unroll
            for (int j = 0; j < 2; j++) {
                int row = arow0 + j * 64;   // n index
                Bs[buf][acol4 * 4 + 0][row] = tf32bits(rb[j].x);
                Bs[buf][acol4 * 4 + 1][row] = tf32bits(rb[j].y);
                Bs[buf][acol4 * 4 + 2][row] = tf32bits(rb[j].z);
                Bs[buf][acol4 * 4 + 3][row] = tf32bits(rb[j].w);
            }
        } else {
            const int brow = tid >> 5;
            const int bc   = (tid & 31) * 4;
            #pragma unroll
            for (int j = 0; j < 2; j++) {
                uint4 u = make_uint4(tf32bits(rb[j].x), tf32bits(rb[j].y),
                                     tf32bits(rb[j].z), tf32bits(rb[j].w));
                *reinterpret_cast<uint4*>(&Bs[buf][brow + j * 8][bc]) = u;
            }
        }
    };

    auto compute = [&](int buf) {
        #pragma unroll
        for (int ks = 0; ks < 2; ks++) {
            const int kb = ks * 8 + (lane & 3);
            unsigned af[4][4], bf[4][2];
            const int mr = wm + (lane >> 2);
            #pragma unroll
            for (int mi = 0; mi < 4; mi++) {
                int m = mr + mi * 16;
                af[mi][0] = As[buf][kb][m];
                af[mi][1] = As[buf][kb][m + 8];
                af[mi][2] = As[buf][kb + 4][m];
                af[mi][3] = As[buf][kb + 4][m + 8];
            }
            const int nr = wn + (lane >> 2);
            #pragma unroll
            for (int ni = 0; ni < 4; ni++) {
                int n = nr + ni * 8;
                bf[ni][0] = Bs[buf][kb][n];
                bf[ni][1] = Bs[buf][kb + 4][n];
            }
            #pragma unroll
            for (int mi = 0; mi < 4; mi++)
                #pragma unroll
                for (int ni = 0; ni < 4; ni++)
                    mma_m16n8k8(acc[mi][ni], af[mi], bf[ni]);
        }
    };

    const int KT = K / BK;
    loadG(0);
    storeS(0);
    __syncthreads();
    for (int kt = 0; kt < KT; kt++) {
        const int buf = kt & 1;
        if (kt + 1 < KT) loadG(kt + 1);
        compute(buf);
        if (kt + 1 < KT) storeS(buf ^ 1);
        __syncthreads();
    }

    // Epilogue
    #pragma unroll
    for (int mi = 0; mi < 4; mi++) {
        const int r = bm0 + wm + (lane >> 2) + mi * 16;
        #pragma unroll
        for (int ni = 0; ni < 4; ni++) {
            const int n = bn0 + wn + ni * 8 + (lane & 3) * 2;
            float bv0 = 0.0f, bv1 = 0.0f;
            if (bias) { bv0 = bias[n]; bv1 = bias[n + 1]; }
            float v0 = acc[mi][ni][0] + bv0;
            float v1 = acc[mi][ni][1] + bv1;
            float v2 = acc[mi][ni][2] + bv0;
            float v3 = acc[mi][ni][3] + bv1;
            if (EPI == 1) {
                v0 = gelu_tanh(v0); v1 = gelu_tanh(v1);
                v2 = gelu_tanh(v2); v3 = gelu_tanh(v3);
            }
            if (Res) {
                v0 += Res[(long long)r * ldc + n];
                v1 += Res[(long long)r * ldc + n + 1];
                v2 += Res[(long long)(r + 8) * ldc + n];
                v3 += Res[(long long)(r + 8) * ldc + n + 1];
            }
            *reinterpret_cast<float2*>(&C[(long long)r * ldc + n]) = make_float2(v0, v1);
            *reinterpret_cast<float2*>(&C[(long long)(r + 8) * ldc + n]) = make_float2(v2, v3);
        }
    }
}

// LayerNorm over rows of 1024. grid = ROWS, 256 threads (1 float4/thread).
__global__ __launch_bounds__(256)
void ln_kernel(const float* __restrict__ x, const float* __restrict__ g,
               const float* __restrict__ b, float* __restrict__ out)
{
    const size_t row = blockIdx.x;
    const float4 v = reinterpret_cast<const float4*>(x + row * D_MODEL)[threadIdx.x];
    float s  = v.x + v.y + v.z + v.w;
    float sq = v.x * v.x + v.y * v.y + v.z * v.z + v.w * v.w;

    __shared__ float rs[8], rq[8];
    #pragma unroll
    for (int o = 16; o; o >>= 1) {
        s  += __shfl_xor_sync(0xffffffffu, s, o);
        sq += __shfl_xor_sync(0xffffffffu, sq, o);
    }
    if ((threadIdx.x & 31) == 0) { rs[threadIdx.x >> 5] = s; rq[threadIdx.x >> 5] = sq; }
    __syncthreads();
    float st = 0.0f, qt = 0.0f;
    #pragma unroll
    for (int i = 0; i < 8; i++) { st += rs[i]; qt += rq[i]; }
    const float mean = st * (1.0f / D_MODEL);
    const float var  = qt * (1.0f / D_MODEL) - mean * mean;
    const float rstd = rsqrtf(var + 1e-5f);

    const float4 gv = reinterpret_cast<const float4*>(g)[threadIdx.x];
    const float4 bv = reinterpret_cast<const float4*>(b)[threadIdx.x];
    float4 o;
    o.x = (v.x - mean) * rstd * gv.x + bv.x;
    o.y = (v.y - mean) * rstd * gv.y + bv.y;
    o.z = (v.z - mean) * rstd * gv.z + bv.z;
    o.w = (v.w - mean) * rstd * gv.w + bv.w;
    reinterpret_cast<float4*>(out + row * D_MODEL)[threadIdx.x] = o;
}

// Causal softmax over scores[B, T, T] with scale 1/8. grid = (T, B), 256 thr.
__global__ __launch_bounds__(256)
void softmax_kernel(float* __restrict__ s)
{
    const int t = blockIdx.x;
    float* row = s + ((size_t)blockIdx.y * T_SEQ + t) * (size_t)T_SEQ;
    const int L = t + 1;
    const float scale = 0.125f;

    float v[8];
    float m = -3.0e38f;
    #pragma unroll
    for (int i = 0; i < 8; i++) {
        const int j = threadIdx.x + i * 256;
        float val = (j < L) ? row[j] * scale : -3.0e38f;
        v[i] = val;
        m = fmaxf(m, val);
    }
    __shared__ float red[8], red2[8];
    #pragma unroll
    for (int o = 16; o; o >>= 1) m = fmaxf(m, __shfl_xor_sync(0xffffffffu, m, o));
    if ((threadIdx.x & 31) == 0) red[threadIdx.x >> 5] = m;
    __syncthreads();
    float bm = red[0];
    #pragma unroll
    for (int i = 1; i < 8; i++) bm = fmaxf(bm, red[i]);

    float sum = 0.0f;
    #pragma unroll
    for (int i = 0; i < 8; i++) {
        const int j = threadIdx.x + i * 256;
        float e = (j < L) ? __expf(v[i] - bm) : 0.0f;
        v[i] = e;
        sum += e;
    }
    #pragma unroll
    for (int o = 16; o; o >>= 1) sum += __shfl_xor_sync(0xffffffffu, sum, o);
    if ((threadIdx.x & 31) == 0) red2[threadIdx.x >> 5] = sum;
    __syncthreads();
    float bs = 0.0f;
    #pragma unroll
    for (int i = 0; i < 8; i++) bs += red2[i];
    const float inv = 1.0f / bs;
    #pragma unroll
    for (int i = 0; i < 8; i++) {
        const int j = threadIdx.x + i * 256;
        row[j] = v[i] * inv;
    }
}

extern "C" void kernel_launch(void* const* d_in, const int* in_sizes, int n_in,
                              void* d_out, int out_size)
{
    const float* x      = (const float*)d_in[0];
    const float* w_attn = (const float*)d_in[1];
    const float* b_attn = (const float*)d_in[2];
    const float* w_proj = (const float*)d_in[3];
    const float* b_proj = (const float*)d_in[4];
    const float* ln1_g  = (const float*)d_in[5];
    const float* ln1_b  = (const float*)d_in[6];
    const float* ln2_g  = (const float*)d_in[7];
    const float* ln2_b  = (const float*)d_in[8];
    const float* w_fc   = (const float*)d_in[9];
    const float* b_fc   = (const float*)d_in[10];
    const float* w_fc2  = (const float*)d_in[11];
    const float* b_fc2  = (const float*)d_in[12];
    float* out = (float*)d_out;

    float *h, *qkv, *sc, *y, *mlp;
    cudaGetSymbolAddress((void**)&h,   g_h);
    cudaGetSymbolAddress((void**)&qkv, g_qkv);
    cudaGetSymbolAddress((void**)&sc,  g_scores);
    cudaGetSymbolAddress((void**)&y,   g_y);
    cudaGetSymbolAddress((void**)&mlp, g_mlp);

    // 1) LN1
    ln_kernel<<<ROWS, 256>>>(x, ln1_g, ln1_b, h);

    // 2) qkv = h @ w_attn + b_attn     [8192,1024]x[1024,3072]
    gemm_kernel<false, 0><<<dim3(3 * D_MODEL / BN, ROWS / BM, 1), 256>>>(
        h, w_attn, b_attn, nullptr, qkv,
        D_MODEL, D_MODEL, 3 * D_MODEL, 3 * D_MODEL, 0, 0, 0);

    // 3) scores = q @ k^T (per batch)  [2048,1024]x[2048,1024]^T
    gemm_kernel<true, 0><<<dim3(T_SEQ / BN, T_SEQ / BM, N_BATCH), 256>>>(
        qkv, qkv + D_MODEL, nullptr, nullptr, sc,
        D_MODEL, 3 * D_MODEL, 3 * D_MODEL, T_SEQ,
        (long long)T_SEQ * 3 * D_MODEL, (long long)T_SEQ * 3 * D_MODEL,
        (long long)T_SEQ * T_SEQ);

    // 4) causal softmax (scale 1/8 folded in)
    softmax_kernel<<<dim3(T_SEQ, N_BATCH), 256>>>(sc);

    // 5) y = att @ v (per batch)       [2048,2048]x[2048,1024]
    gemm_kernel<false, 0><<<dim3(D_MODEL / BN, T_SEQ / BM, N_BATCH), 256>>>(
        sc, qkv + 2 * D_MODEL, nullptr, nullptr, y,
        T_SEQ, T_SEQ, 3 * D_MODEL, D_MODEL,
        (long long)T_SEQ * T_SEQ, (long long)T_SEQ * 3 * D_MODEL,
        (long long)T_SEQ * D_MODEL);

    // 6) x1 = x + y @ w_proj + b_proj  -> out
    gemm_kernel<false, 0><<<dim3(D_MODEL / BN, ROWS / BM, 1), 256>>>(
        y, w_proj, b_proj, x, out,
        D_MODEL, D_MODEL, D_MODEL, D_MODEL, 0, 0, 0);

    // 7) LN2
    ln_kernel<<<ROWS, 256>>>(out, ln2_g, ln2_b, h);

    // 8) mlp = gelu(h @ w_fc + b_fc)   [8192,1024]x[1024,4096]
    gemm_kernel<false, 1><<<dim3(4 * D_MODEL / BN, ROWS / BM, 1), 256>>>(
        h, w_fc, b_fc, nullptr, mlp,
        D_MODEL, D_MODEL, 4 * D_MODEL, 4 * D_MODEL, 0, 0, 0);

    // 9) out = out + mlp @ w_fc2 + b_fc2
    gemm_kernel<false, 0><<<dim3(D_MODEL / BN, ROWS / BM, 1), 256>>>(
        mlp, w_fc2, b_fc2, out, out,
        4 * D_MODEL, 4 * D_MODEL, D_MODEL, D_MODEL, 0, 0, 0);
}

// round 3
// speedup vs baseline: 2.8612x; 2.8612x over previous
#include <cuda_runtime.h>
#include <cuda_fp16.h>
#include <cstdint>

// ---------------------------------------------------------------------------
// GPT block, fp16 mma.sync (m16n8k16, fp32 accum) everywhere.
// NOTE: tcgen05 is unavailable — harness compiles via compute_103 virtual PTX
// which rejects all 'a'-feature instructions. mma.sync is the tensor path.
// All GEMMs NT: C[M,N] = A[M,K] @ B[N,K]^T, fp16 operands in gmem.
// ---------------------------------------------------------------------------

#define D_MODEL 1024
#define T_SEQ   2048
#define N_BATCH 4
#define ROWS    (N_BATCH * T_SEQ)   // 8192

__device__ __half g_h16[ROWS * D_MODEL];
__device__ __half g_w16[12582912];
__device__ __half g_qkv16[(size_t)ROWS * 3 * D_MODEL];
__device__ __half g_vT16[(size_t)N_BATCH * D_MODEL * T_SEQ];
__device__ float  g_sc[(size_t)N_BATCH * T_SEQ * T_SEQ];
__device__ __half g_p16[(size_t)N_BATCH * T_SEQ * T_SEQ];
__device__ __half g_y16[ROWS * D_MODEL];
__device__ __half g_mlp16[(size_t)ROWS * 4 * D_MODEL];

#define OFF_PROJ 3145728
#define OFF_FC   4194304
#define OFF_FC2  8388608

// smem: 3 stages x (A 128x80B + B 128x80B) = 3 x 20480 = 61440 bytes
#define STAGE_BYTES 20480
#define SMEM_BYTES  61440

__device__ __forceinline__ uint32_t smem_u32(const void* p) {
    uint32_t a;
    asm("{ .reg .u64 t; cvta.to.shared.u64 t, %1; cvt.u32.u64 %0, t; }" : "=r"(a) : "l"(p));
    return a;
}
__device__ __forceinline__ void cp_async16(uint32_t dst, const void* src) {
    asm volatile("cp.async.cg.shared.global [%0], [%1], 16;" :: "r"(dst), "l"(src));
}
#define CP_COMMIT() asm volatile("cp.async.commit_group;" ::: "memory")
#define CP_WAIT1()  asm volatile("cp.async.wait_group 1;" ::: "memory")

__device__ __forceinline__ void ldsm4(uint32_t& r0, uint32_t& r1, uint32_t& r2,
                                      uint32_t& r3, uint32_t addr) {
    asm volatile("ldmatrix.sync.aligned.m8n8.x4.shared.b16 {%0,%1,%2,%3}, [%4];"
                 : "=r"(r0), "=r"(r1), "=r"(r2), "=r"(r3) : "r"(addr));
}
__device__ __forceinline__ void mma16816(float* c, const uint32_t* a, const uint32_t* b) {
    asm volatile(
        "mma.sync.aligned.m16n8k16.row.col.f32.f16.f16.f32 "
        "{%0,%1,%2,%3},{%4,%5,%6,%7},{%8,%9},{%0,%1,%2,%3};"
        : "+f"(c[0]), "+f"(c[1]), "+f"(c[2]), "+f"(c[3])
        : "r"(a[0]), "r"(a[1]), "r"(a[2]), "r"(a[3]), "r"(b[0]), "r"(b[1]));
}
__device__ __forceinline__ float gelu_f(float x) {
    float u = 0.7978845608028654f * (x + 0.044715f * x * x * x);
    return x / (1.0f + __expf(-2.0f * u));   // x*sigmoid(2u) == 0.5x(1+tanh u)
}

// ---------------------------------------------------------------------------
// CAUSAL: 0 none, 1 skip fully-masked blocks, 2 truncate K at diagonal
// EPI:    0 none, 1 +bias, 2 +bias+Res, 3 gelu(x+bias)
// OUTH:   1 -> fp16 output, 0 -> fp32 output
// ---------------------------------------------------------------------------
template<int CAUSAL, int EPI, int OUTH>
__global__ __launch_bounds__(256, 2)
void hgemm(const __half* __restrict__ A, const __half* __restrict__ B,
           const float* __restrict__ bias, const float* __restrict__ Res,
           void* __restrict__ Cv, int K, int lda, int ldb, int ldc,
           long long sA, long long sB, long long sC)
{
    extern __shared__ char smem[];
    const int bm0 = blockIdx.y * 128, bn0 = blockIdx.x * 128;
    if (CAUSAL == 1 && bn0 >= bm0 + 128) return;

    A += blockIdx.z * sA;
    B += blockIdx.z * sB;

    const int tid = threadIdx.x, lane = tid & 31, wid = tid >> 5;
    const int wm = (wid >> 2) * 64, wn = (wid & 3) * 32;
    const uint32_t sb0 = smem_u32(smem);

    int KT = K >> 5;
    if (CAUSAL == 2) { int lim = (bm0 + 128) >> 5; if (lim < KT) KT = lim; }

    float acc[4][4][4] = {};

    auto issue = [&](int buf, int kt) {
        const __half* Ag = A + (long long)bm0 * lda + kt * 32;
        const __half* Bg = B + (long long)bn0 * ldb + kt * 32;
        const uint32_t sa = sb0 + buf * STAGE_BYTES, sbB = sa + 10240;
        #pragma unroll
        for (int i = 0; i < 2; i++) {
            const int id = tid + i * 256;
            const int row = id >> 2, ch = id & 3;
            cp_async16(sa  + row * 80 + ch * 16, Ag + (long long)row * lda + ch * 8);
            cp_async16(sbB + row * 80 + ch * 16, Bg + (long long)row * ldb + ch * 8);
        }
    };

    issue(0, 0); CP_COMMIT();
    issue(1, 1); CP_COMMIT();   // KT >= 4 always here

    const int rlow = ((lane >> 3) & 1) * 8 + (lane & 7);  // ldmatrix row within 16
    const int chq  = lane >> 4;                           // k-chunk select (+8 halfs)

    for (int kt = 0; kt < KT; ++kt) {
        CP_WAIT1();
        __syncthreads();
        const int buf = kt - (kt / 3) * 3;
        const uint32_t sa = sb0 + buf * STAGE_BYTES, sbB = sa + 10240;
        #pragma unroll
        for (int ks = 0; ks < 2; ks++) {
            uint32_t af[4][4], bf[2][4];
            #pragma unroll
            for (int mi = 0; mi < 4; mi++)
                ldsm4(af[mi][0], af[mi][1], af[mi][2], af[mi][3],
                      sa + (wm + mi * 16 + rlow) * 80 + (ks * 2 + chq) * 16);
            #pragma unroll
            for (int nj = 0; nj < 2; nj++)
                ldsm4(bf[nj][0], bf[nj][1], bf[nj][2], bf[nj][3],
                      sbB + (wn + nj * 16 + rlow) * 80 + (ks * 2 + chq) * 16);
            #pragma unroll
            for (int mi = 0; mi < 4; mi++)
                #pragma unroll
                for (int ni = 0; ni < 4; ni++) {
                    uint32_t bb[2] = { bf[ni >> 1][ni & 1], bf[ni >> 1][2 + (ni & 1)] };
                    mma16816(acc[mi][ni], af[mi], bb);
                }
        }
        const int nf = kt + 2;
        if (nf < KT) issue(nf - (nf / 3) * 3, nf);
        CP_COMMIT();
    }

    // Epilogue
    const int g = lane >> 2, t2 = (lane & 3) * 2;
    #pragma unroll
    for (int mi = 0; mi < 4; mi++) {
        const long long m0 = bm0 + wm + mi * 16 + g;
        #pragma unroll
        for (int ni = 0; ni < 4; ni++) {
            const int n = bn0 + wn + ni * 8 + t2;
            float v0 = acc[mi][ni][0], v1 = acc[mi][ni][1];
            float v2 = acc[mi][ni][2], v3 = acc[mi][ni][3];
            if (EPI >= 1) {
                const float b0 = bias[n], b1 = bias[n + 1];
                v0 += b0; v1 += b1; v2 += b0; v3 += b1;
            }
            if (EPI == 3) {
                v0 = gelu_f(v0); v1 = gelu_f(v1); v2 = gelu_f(v2); v3 = gelu_f(v3);
            }
            if (EPI == 2) {
                v0 += Res[m0 * ldc + n];       v1 += Res[m0 * ldc + n + 1];
                v2 += Res[(m0 + 8) * ldc + n]; v3 += Res[(m0 + 8) * ldc + n + 1];
            }
            if (OUTH) {
                __half* C = (__half*)Cv + blockIdx.z * sC;
                *(__half2*)(C + m0 * ldc + n)       = __floats2half2_rn(v0, v1);
                *(__half2*)(C + (m0 + 8) * ldc + n) = __floats2half2_rn(v2, v3);
            } else {
                float* C = (float*)Cv + blockIdx.z * sC;
                *(float2*)(C + m0 * ldc + n)       = make_float2(v0, v1);
                *(float2*)(C + (m0 + 8) * ldc + n) = make_float2(v2, v3);
            }
        }
    }
}

// ---------------- transpose fp32 -> fp16 (weights) ----------------
__global__ __launch_bounds__(256)
void transpose_f2h(const float* __restrict__ in, __half* __restrict__ out,
                   int ldi, int ldo)
{
    __shared__ float t[32][33];
    const int c0 = blockIdx.x * 32, r0 = blockIdx.y * 32;
    #pragma unroll
    for (int j = 0; j < 32; j += 8)
        t[threadIdx.y + j][threadIdx.x] =
            in[(long long)(r0 + threadIdx.y + j) * ldi + c0 + threadIdx.x];
    __syncthreads();
    #pragma unroll
    for (int j = 0; j < 32; j += 8)
        out[(long long)(c0 + threadIdx.y + j) * ldo + r0 + threadIdx.x] =
            __float2half(t[threadIdx.x][threadIdx.y + j]);
}

// ---------------- transpose fp16 -> fp16 (V), batched ----------------
__global__ __launch_bounds__(256)
void transpose_h2h(const __half* __restrict__ in, __half* __restrict__ out,
                   int ldi, int ldo, long long sIn, long long sOut)
{
    __shared__ __half t[32][34];
    in  += blockIdx.z * sIn;
    out += blockIdx.z * sOut;
    const int c0 = blockIdx.x * 32, r0 = blockIdx.y * 32;
    #pragma unroll
    for (int j = 0; j < 32; j += 8)
        t[threadIdx.y + j][threadIdx.x] =
            in[(long long)(r0 + threadIdx.y + j) * ldi + c0 + threadIdx.x];
    __syncthreads();
    #pragma unroll
    for (int j = 0; j < 32; j += 8)
        out[(long long)(c0 + threadIdx.y + j) * ldo + r0 + threadIdx.x] =
            t[threadIdx.x][threadIdx.y + j];
}

// ---------------- LayerNorm (rows of 1024), fp16 output ----------------
__global__ __launch_bounds__(256)
void ln_kernel(const float* __restrict__ x, const float* __restrict__ g,
               const float* __restrict__ b, __half* __restrict__ out)
{
    const size_t row = blockIdx.x;
    const float4 v = reinterpret_cast<const float4*>(x + row * D_MODEL)[threadIdx.x];
    float s  = v.x + v.y + v.z + v.w;
    float sq = v.x * v.x + v.y * v.y + v.z * v.z + v.w * v.w;

    __shared__ float rs[8], rq[8];
    #pragma unroll
    for (int o = 16; o; o >>= 1) {
        s  += __shfl_xor_sync(0xffffffffu, s, o);
        sq += __shfl_xor_sync(0xffffffffu, sq, o);
    }
    if ((threadIdx.x & 31) == 0) { rs[threadIdx.x >> 5] = s; rq[threadIdx.x >> 5] = sq; }
    __syncthreads();
    float st = 0.0f, qt = 0.0f;
    #pragma unroll
    for (int i = 0; i < 8; i++) { st += rs[i]; qt += rq[i]; }
    const float mean = st * (1.0f / D_MODEL);
    const float var  = qt * (1.0f / D_MODEL) - mean * mean;
    const float rstd = rsqrtf(var + 1e-5f);

    const float4 gv = reinterpret_cast<const float4*>(g)[threadIdx.x];
    const float4 bv = reinterpret_cast<const float4*>(b)[threadIdx.x];
    const float o0 = (v.x - mean) * rstd * gv.x + bv.x;
    const float o1 = (v.y - mean) * rstd * gv.y + bv.y;
    const float o2 = (v.z - mean) * rstd * gv.z + bv.z;
    const float o3 = (v.w - mean) * rstd * gv.w + bv.w;
    __half2* op = reinterpret_cast<__half2*>(out + row * D_MODEL);
    op[2 * threadIdx.x]     = __floats2half2_rn(o0, o1);
    op[2 * threadIdx.x + 1] = __floats2half2_rn(o2, o3);
}

// ---------------- causal softmax: fp32 scores -> fp16 probs ----------------
__global__ __launch_bounds__(256)
void softmax_kernel(const float* __restrict__ s, __half* __restrict__ p)
{
    const int t = blockIdx.x;
    const size_t roff = ((size_t)blockIdx.y * T_SEQ + t) * (size_t)T_SEQ;
    const float* row = s + roff;
    __half* prow = p + roff;
    const int L = t + 1;

    float v[8];
    float m = -3.0e38f;
    #pragma unroll
    for (int i = 0; i < 8; i++) {
        const int j = threadIdx.x + i * 256;
        float val = (j < L) ? row[j] * 0.125f : -3.0e38f;
        v[i] = val;
        m = fmaxf(m, val);
    }
    __shared__ float red[8], red2[8];
    #pragma unroll
    for (int o = 16; o; o >>= 1) m = fmaxf(m, __shfl_xor_sync(0xffffffffu, m, o));
    if ((threadIdx.x & 31) == 0) red[threadIdx.x >> 5] = m;
    __syncthreads();
    float bm = red[0];
    #pragma unroll
    for (int i = 1; i < 8; i++) bm = fmaxf(bm, red[i]);

    float sum = 0.0f;
    #pragma unroll
    for (int i = 0; i < 8; i++) {
        const int j = threadIdx.x + i * 256;
        float e = (j < L) ? __expf(v[i] - bm) : 0.0f;
        v[i] = e;
        sum += e;
    }
    #pragma unroll
    for (int o = 16; o; o >>= 1) sum += __shfl_xor_sync(0xffffffffu, sum, o);
    if ((threadIdx.x & 31) == 0) red2[threadIdx.x >> 5] = sum;
    __syncthreads();
    float bs = 0.0f;
    #pragma unroll
    for (int i = 0; i < 8; i++) bs += red2[i];
    const float inv = 1.0f / bs;
    #pragma unroll
    for (int i = 0; i < 8; i++)
        prow[threadIdx.x + i * 256] = __float2half(v[i] * inv);
}

// ---------------------------------------------------------------------------
extern "C" void kernel_launch(void* const* d_in, const int* in_sizes, int n_in,
                              void* d_out, int out_size)
{
    const float* x      = (const float*)d_in[0];
    const float* w_attn = (const float*)d_in[1];
    const float* b_attn = (const float*)d_in[2];
    const float* w_proj = (const float*)d_in[3];
    const float* b_proj = (const float*)d_in[4];
    const float* ln1_g  = (const float*)d_in[5];
    const float* ln1_b  = (const float*)d_in[6];
    const float* ln2_g  = (const float*)d_in[7];
    const float* ln2_b  = (const float*)d_in[8];
    const float* w_fc   = (const float*)d_in[9];
    const float* b_fc   = (const float*)d_in[10];
    const float* w_fc2  = (const float*)d_in[11];
    const float* b_fc2  = (const float*)d_in[12];
    float* out = (float*)d_out;

    __half *h16, *w16, *qkv16, *vT16, *p16, *y16, *mlp16;
    float  *sc;
    cudaGetSymbolAddress((void**)&h16,   g_h16);
    cudaGetSymbolAddress((void**)&w16,   g_w16);
    cudaGetSymbolAddress((void**)&qkv16, g_qkv16);
    cudaGetSymbolAddress((void**)&vT16,  g_vT16);
    cudaGetSymbolAddress((void**)&sc,    g_sc);
    cudaGetSymbolAddress((void**)&p16,   g_p16);
    cudaGetSymbolAddress((void**)&y16,   g_y16);
    cudaGetSymbolAddress((void**)&mlp16, g_mlp16);

    cudaFuncSetAttribute(hgemm<0,1,1>, cudaFuncAttributeMaxDynamicSharedMemorySize, SMEM_BYTES);
    cudaFuncSetAttribute(hgemm<1,0,0>, cudaFuncAttributeMaxDynamicSharedMemorySize, SMEM_BYTES);
    cudaFuncSetAttribute(hgemm<2,0,1>, cudaFuncAttributeMaxDynamicSharedMemorySize, SMEM_BYTES);
    cudaFuncSetAttribute(hgemm<0,2,0>, cudaFuncAttributeMaxDynamicSharedMemorySize, SMEM_BYTES);
    cudaFuncSetAttribute(hgemm<0,3,1>, cudaFuncAttributeMaxDynamicSharedMemorySize, SMEM_BYTES);

    const long long sQ = (long long)T_SEQ * 3 * D_MODEL;
    const long long sS = (long long)T_SEQ * T_SEQ;
    const long long sV = (long long)D_MODEL * T_SEQ;
    const long long sY = (long long)T_SEQ * D_MODEL;

    // weight transposes + fp16 conversion
    transpose_f2h<<<dim3(96, 32),  dim3(32, 8)>>>(w_attn, w16,            3072, 1024);
    transpose_f2h<<<dim3(32, 32),  dim3(32, 8)>>>(w_proj, w16 + OFF_PROJ, 1024, 1024);
    transpose_f2h<<<dim3(128, 32), dim3(32, 8)>>>(w_fc,   w16 + OFF_FC,   4096, 1024);
    transpose_f2h<<<dim3(32, 128), dim3(32, 8)>>>(w_fc2,  w16 + OFF_FC2,  1024, 4096);

    // LN1 -> h16
    ln_kernel<<<ROWS, 256>>>(x, ln1_g, ln1_b, h16);

    // qkv = h @ w_attn + b_attn  (fp16 out)
    hgemm<0,1,1><<<dim3(24, 64, 1), 256, SMEM_BYTES>>>(
        h16, w16, b_attn, nullptr, qkv16, 1024, 1024, 1024, 3072, 0, 0, 0);

    // vT = v^T per batch
    transpose_h2h<<<dim3(32, 64, N_BATCH), dim3(32, 8)>>>(
        qkv16 + 2 * D_MODEL, vT16, 3072, 2048, sQ, sV);

    // scores = q @ k^T (causal block skip, fp32 out)
    hgemm<1,0,0><<<dim3(16, 16, N_BATCH), 256, SMEM_BYTES>>>(
        qkv16, qkv16 + D_MODEL, nullptr, nullptr, sc,
        1024, 3072, 3072, 2048, sQ, sQ, sS);

    // softmax -> fp16 probs
    softmax_kernel<<<dim3(T_SEQ, N_BATCH), 256>>>(sc, p16);

    // y = probs @ v  (K truncated at diagonal, fp16 out)
    hgemm<2,0,1><<<dim3(8, 16, N_BATCH), 256, SMEM_BYTES>>>(
        p16, vT16, nullptr, nullptr, y16, 2048, 2048, 2048, 1024, sS, sV, sY);

    // out = x + y @ w_proj + b_proj  (fp32 out)
    hgemm<0,2,0><<<dim3(8, 64, 1), 256, SMEM_BYTES>>>(
        y16, w16 + OFF_PROJ, b_proj, x, out, 1024, 1024, 1024, 1024, 0, 0, 0);

    // LN2 -> h16
    ln_kernel<<<ROWS, 256>>>(out, ln2_g, ln2_b, h16);

    // mlp = gelu(h @ w_fc + b_fc)  (fp16 out)
    hgemm<0,3,1><<<dim3(32, 64, 1), 256, SMEM_BYTES>>>(
        h16, w16 + OFF_FC, b_fc, nullptr, mlp16, 1024, 1024, 1024, 4096, 0, 0, 0);

    // out = out + mlp @ w_fc2 + b_fc2  (fp32 out)
    hgemm<0,2,0><<<dim3(8, 64, 1), 256, SMEM_BYTES>>>(
        mlp16, w16 + OFF_FC2, b_fc2, out, out, 4096, 4096, 4096, 1024, 0, 0, 0);
}